// round 1
// baseline (speedup 1.0000x reference)
#include <cuda_runtime.h>
#include <cstdint>
#include <math.h>

#define B_  1024
#define V_  50257
#define E_  128
#define NT_ 393          // ceil(V_/128)
#define LDS 132          // 128 + 4 pad (bank-conflict-free mma frag loads)

// ---- scratch (no allocations allowed) ----
__device__ int    g_idx[B_];
__device__ float  g_y[B_ * E_];
__device__ float2 g_part[B_ * NT_];
__device__ float  g_lse[B_];

// round fp32 -> tf32 (RN) once at smem-store time
__device__ __forceinline__ float tf32r(float x) {
    uint32_t u;
    asm("cvt.rna.tf32.f32 %0, %1;" : "=r"(u) : "f"(x));
    return __uint_as_float(u);
}

// ---------------- K1: recover one-hot indices (bandwidth-bound scan) --------
__global__ void find_idx_kernel(const float4* __restrict__ xs4) {
    const long n4 = (long)B_ * V_ / 4;   // 51,463,168 / 4, base is 16B-aligned
    for (long i = blockIdx.x * (long)blockDim.x + threadIdx.x; i < n4;
         i += (long)gridDim.x * blockDim.x) {
        float4 v = xs4[i];
        if (v.x != 0.f || v.y != 0.f || v.z != 0.f || v.w != 0.f) {
            float vals[4] = {v.x, v.y, v.z, v.w};
            long base = i * 4;
#pragma unroll
            for (int j = 0; j < 4; j++) {
                if (vals[j] != 0.f) {
                    long p = base + j;
                    int  b = (int)(p / V_);
                    g_idx[b] = (int)(p - (long)b * V_);
                }
            }
        }
    }
}

// ---------------- K2: y[b] = EMBEDM[idx[b]] @ metric  (fp32, tiny) ----------
__global__ void embed_metric_kernel(const float* __restrict__ EMB,
                                    const float* __restrict__ metric) {
    __shared__ float xe[E_];
    const int b = blockIdx.x, t = threadIdx.x;   // 128 threads
    const int idx = g_idx[b];
    xe[t] = EMB[(size_t)idx * E_ + t];
    __syncthreads();
    float acc = 0.f;
#pragma unroll 8
    for (int k = 0; k < E_; k++) acc += xe[k] * metric[k * E_ + t];
    g_y[b * E_ + t] = acc;
}

// ---------------- K3: scores GEMM (tf32 mma) + per-tile softmax partials ----
// CTA tile 128x128, K=128 consumed in one shot (16 k-steps of m16n8k8).
// 8 warps: warp_m in {0,1} (64 rows), warp_n in {0..3} (32 cols).
__global__ void __launch_bounds__(256, 1)
gemm_lse_kernel(const float* __restrict__ neg, float* __restrict__ out) {
    extern __shared__ float smem[];
    float* As = smem;               // [128][LDS]
    float* Bs = smem + 128 * LDS;   // [128][LDS]

    const int tid = threadIdx.x;
    const int n0  = blockIdx.x * 128;
    const int m0  = blockIdx.y * 128;

    // Load A tile (g_y, always full) -> tf32 rounded
#pragma unroll
    for (int f = tid; f < 128 * 32; f += 256) {
        int r  = f >> 5;
        int k4 = (f & 31) << 2;
        float4 v = *reinterpret_cast<const float4*>(g_y + (m0 + r) * E_ + k4);
        As[r * LDS + k4 + 0] = tf32r(v.x);
        As[r * LDS + k4 + 1] = tf32r(v.y);
        As[r * LDS + k4 + 2] = tf32r(v.z);
        As[r * LDS + k4 + 3] = tf32r(v.w);
    }
    // Load B tile (NEGEMBEDM rows n0..n0+127, zero-padded past V)
#pragma unroll
    for (int f = tid; f < 128 * 32; f += 256) {
        int n  = f >> 5;
        int k4 = (f & 31) << 2;
        float4 v = make_float4(0.f, 0.f, 0.f, 0.f);
        if (n0 + n < V_)
            v = *reinterpret_cast<const float4*>(neg + (size_t)(n0 + n) * E_ + k4);
        Bs[n * LDS + k4 + 0] = tf32r(v.x);
        Bs[n * LDS + k4 + 1] = tf32r(v.y);
        Bs[n * LDS + k4 + 2] = tf32r(v.z);
        Bs[n * LDS + k4 + 3] = tf32r(v.w);
    }
    __syncthreads();

    const int wid = tid >> 5, lane = tid & 31;
    const int warp_m = wid & 1, warp_n = wid >> 1;
    const int qid = lane >> 2, tig = lane & 3;

    float c[4][4][4];
#pragma unroll
    for (int mi = 0; mi < 4; mi++)
#pragma unroll
        for (int ni = 0; ni < 4; ni++)
#pragma unroll
            for (int j = 0; j < 4; j++) c[mi][ni][j] = 0.f;

#pragma unroll
    for (int ks = 0; ks < 16; ks++) {
        const int k0 = ks * 8;
        uint32_t a[4][4], bf[4][2];
#pragma unroll
        for (int mi = 0; mi < 4; mi++) {
            int r0 = warp_m * 64 + mi * 16 + qid;
            a[mi][0] = __float_as_uint(As[r0 * LDS + k0 + tig]);
            a[mi][1] = __float_as_uint(As[(r0 + 8) * LDS + k0 + tig]);
            a[mi][2] = __float_as_uint(As[r0 * LDS + k0 + tig + 4]);
            a[mi][3] = __float_as_uint(As[(r0 + 8) * LDS + k0 + tig + 4]);
        }
#pragma unroll
        for (int ni = 0; ni < 4; ni++) {
            int bn = warp_n * 32 + ni * 8 + qid;
            bf[ni][0] = __float_as_uint(Bs[bn * LDS + k0 + tig]);
            bf[ni][1] = __float_as_uint(Bs[bn * LDS + k0 + tig + 4]);
        }
#pragma unroll
        for (int mi = 0; mi < 4; mi++)
#pragma unroll
            for (int ni = 0; ni < 4; ni++)
                asm volatile(
                    "mma.sync.aligned.m16n8k8.row.col.f32.tf32.tf32.f32 "
                    "{%0,%1,%2,%3},{%4,%5,%6,%7},{%8,%9},{%0,%1,%2,%3};"
                    : "+f"(c[mi][ni][0]), "+f"(c[mi][ni][1]),
                      "+f"(c[mi][ni][2]), "+f"(c[mi][ni][3])
                    : "r"(a[mi][0]), "r"(a[mi][1]), "r"(a[mi][2]), "r"(a[mi][3]),
                      "r"(bf[ni][0]), "r"(bf[ni][1]));
    }
    __syncthreads();   // done with As/Bs; reuse As as C tile

    float* Cs = As;
#pragma unroll
    for (int mi = 0; mi < 4; mi++) {
#pragma unroll
        for (int ni = 0; ni < 4; ni++) {
            int r0 = warp_m * 64 + mi * 16 + qid;
            int c0 = warp_n * 32 + ni * 8 + tig * 2;
            Cs[r0 * LDS + c0]           = c[mi][ni][0];
            Cs[r0 * LDS + c0 + 1]       = c[mi][ni][1];
            Cs[(r0 + 8) * LDS + c0]     = c[mi][ni][2];
            Cs[(r0 + 8) * LDS + c0 + 1] = c[mi][ni][3];
        }
    }
    __syncthreads();

    const int nvalid = min(128, V_ - n0);
    // coalesced store of raw scores
    for (int f = tid; f < 128 * 128; f += 256) {
        int r = f >> 7, cc = f & 127;
        if (cc < nvalid)
            out[(size_t)(m0 + r) * V_ + n0 + cc] = Cs[r * LDS + cc];
    }
    // per-(row, tile) online-softmax partial
    if (tid < 128) {
        const int r = tid;
        float m = -INFINITY;
        for (int cc = 0; cc < nvalid; cc++) m = fmaxf(m, Cs[r * LDS + cc]);
        float l = 0.f;
        for (int cc = 0; cc < nvalid; cc++) l += expf(Cs[r * LDS + cc] - m);
        g_part[(size_t)(m0 + r) * NT_ + blockIdx.x] = make_float2(m, l);
    }
}

// ---------------- K4: combine partials -> lse[b] ----------------------------
__global__ void lse_kernel() {
    const int b = blockIdx.x, t = threadIdx.x;   // 128 threads
    __shared__ float sm[128], sl[128];
    float m = -INFINITY, l = 0.f;
    for (int i = t; i < NT_; i += 128) {
        float2 p = g_part[(size_t)b * NT_ + i];
        float nm = fmaxf(m, p.x);
        l = l * expf(m - nm) + p.y * expf(p.x - nm);
        m = nm;
    }
    sm[t] = m; sl[t] = l;
    __syncthreads();
    for (int s = 64; s > 0; s >>= 1) {
        if (t < s) {
            float m2 = sm[t + s], l2 = sl[t + s];
            float nm = fmaxf(sm[t], m2);
            sl[t] = sl[t] * expf(sm[t] - nm) + l2 * expf(m2 - nm);
            sm[t] = nm;
        }
        __syncthreads();
    }
    if (t == 0) g_lse[b] = sm[0] + logf(sl[0]);
}

// ---------------- K5: out = scores - lse[b] ---------------------------------
__global__ void sub_kernel(float* __restrict__ out) {
    const int b = blockIdx.y;
    const int v = blockIdx.x * blockDim.x + threadIdx.x;
    if (v < V_) {
        size_t i = (size_t)b * V_ + v;
        out[i] -= g_lse[b];
    }
}

extern "C" void kernel_launch(void* const* d_in, const int* in_sizes, int n_in,
                              void* d_out, int out_size) {
    const float* xs     = (const float*)d_in[0];
    const float* metric = (const float*)d_in[1];
    const float* EMB    = (const float*)d_in[2];
    const float* NEG    = (const float*)d_in[3];
    float* out = (float*)d_out;

    find_idx_kernel<<<2048, 256>>>((const float4*)xs);
    embed_metric_kernel<<<B_, 128>>>(EMB, metric);

    const size_t smem = 2 * 128 * LDS * sizeof(float);   // 135168 B
    cudaFuncSetAttribute(gemm_lse_kernel,
                         cudaFuncAttributeMaxDynamicSharedMemorySize, (int)smem);
    gemm_lse_kernel<<<dim3(NT_, 8), 256, smem>>>(NEG, out);

    lse_kernel<<<B_, 128>>>();
    sub_kernel<<<dim3((V_ + 255) / 256, B_), 256>>>(out);
}

// round 3
// speedup vs baseline: 1.2620x; 1.2620x over previous
#include <cuda_runtime.h>
#include <cstdint>
#include <math.h>

#define B_  1024
#define V_  50257
#define E_  128
#define NT_ 393          // ceil(V_/128)
#define TPAD 132         // padded tile stride (floats): conflict-free frag LDS

// ---- scratch (no allocations allowed) ----
__device__ int    g_idx[B_];
__device__ float  g_y[B_ * E_];
__device__ float2 g_part[B_ * NT_];
__device__ float  g_lse[B_];

__device__ __forceinline__ float tf32r(float x) {
    uint32_t u;
    asm("cvt.rna.tf32.f32 %0, %1;" : "=r"(u) : "f"(x));
    return __uint_as_float(u);
}
__device__ __forceinline__ uint32_t smem_u32(const void* p) {
    uint32_t a;
    asm("{ .reg .u64 t; cvta.to.shared.u64 t, %1; cvt.u32.u64 %0, t; }"
        : "=r"(a) : "l"(p));
    return a;
}

// ---------------- K1: recover one-hot indices (bandwidth-bound scan) --------
__global__ void find_idx_kernel(const float4* __restrict__ xs4) {
    const long n4 = (long)B_ * V_ / 4;
    for (long i = blockIdx.x * (long)blockDim.x + threadIdx.x; i < n4;
         i += (long)gridDim.x * blockDim.x) {
        float4 v = xs4[i];
        if (v.x != 0.f || v.y != 0.f || v.z != 0.f || v.w != 0.f) {
            float vals[4] = {v.x, v.y, v.z, v.w};
            long base = i * 4;
#pragma unroll
            for (int j = 0; j < 4; j++) {
                if (vals[j] != 0.f) {
                    long p = base + j;
                    int  b = (int)(p / V_);
                    g_idx[b] = (int)(p - (long)b * V_);
                }
            }
        }
    }
}

// ---------------- K2: y[b] = EMBEDM[idx[b]] @ metric ------------------------
__global__ void embed_metric_kernel(const float* __restrict__ EMB,
                                    const float* __restrict__ metric) {
    __shared__ float xe[E_];
    const int b = blockIdx.x, t = threadIdx.x;   // 128 threads
    const int idx = g_idx[b];
    xe[t] = EMB[(size_t)idx * E_ + t];
    __syncthreads();
    float acc = 0.f;
#pragma unroll 8
    for (int k = 0; k < E_; k++) acc += xe[k] * metric[k * E_ + t];
    g_y[b * E_ + t] = acc;
}

// ---------------- K3: persistent double-buffered tf32 GEMM + partials -------
// smem (floats): As[128*132] | Bs0[128*132] | Bs1[128*132] | part float2[128][4]
#define A_OFF   0
#define B0_OFF  16896
#define B1_OFF  33792
#define P_OFF   50688
#define SMEM_BYTES (50688 * 4 + 4096)   // 206848

__global__ void __launch_bounds__(256, 1)
gemm_lse_tc(const float* __restrict__ neg, float* __restrict__ out) {
    extern __shared__ float sm[];
    float* As = sm + A_OFF;
    float2* prt = reinterpret_cast<float2*>(sm + P_OFF);

    const int tid = threadIdx.x;
    const int wid = tid >> 5, lane = tid & 31;
    const int warp_m = wid & 1, warp_n = wid >> 1;
    const int qid = lane >> 2, tig = lane & 3;
    const int m0 = blockIdx.y * 128;

    // ---- load A tile once (g_y m-block), RNA tf32 convert ----
#pragma unroll
    for (int f = tid; f < 4096; f += 256) {
        int r = f >> 5, k4 = (f & 31) << 2;
        float4 v = *reinterpret_cast<const float4*>(g_y + (m0 + r) * E_ + k4);
        v.x = tf32r(v.x); v.y = tf32r(v.y); v.z = tf32r(v.z); v.w = tf32r(v.w);
        *reinterpret_cast<float4*>(As + r * TPAD + k4) = v;
    }

    const uint32_t b_smem[2] = { smem_u32(sm + B0_OFF), smem_u32(sm + B1_OFF) };

    // issue cp.async for B tile nt into buffer buf (zero-fill past V)
    auto issueB = [&](int nt, int buf) {
        const int n0 = nt * 128;
        const char* base = reinterpret_cast<const char*>(neg) + (size_t)n0 * 512;
        const uint32_t d0 = b_smem[buf];
#pragma unroll
        for (int c = tid; c < 4096; c += 256) {
            int row = c >> 5, off = (c & 31) * 16;
            uint32_t dst = d0 + row * (TPAD * 4) + off;
            const char* src = base + (size_t)row * 512 + off;
            uint32_t sz = (n0 + row < V_) ? 16u : 0u;
            asm volatile("cp.async.cg.shared.global [%0], [%1], 16, %2;"
                         :: "r"(dst), "l"(src), "r"(sz) : "memory");
        }
        asm volatile("cp.async.commit_group;" ::: "memory");
    };

    issueB(blockIdx.x, 0);
    int buf = 0;
    for (int nt = blockIdx.x; nt < NT_; nt += gridDim.x, buf ^= 1) {
        const int ntn = nt + gridDim.x;
        if (ntn < NT_) issueB(ntn, buf ^ 1);
        else asm volatile("cp.async.commit_group;" ::: "memory");
        asm volatile("cp.async.wait_group 1;" ::: "memory");
        __syncthreads();

        const float* Bs = sm + (buf ? B1_OFF : B0_OFF);

        float c[4][4][4];
#pragma unroll
        for (int mi = 0; mi < 4; mi++)
#pragma unroll
            for (int ni = 0; ni < 4; ni++)
#pragma unroll
                for (int j = 0; j < 4; j++) c[mi][ni][j] = 0.f;

#pragma unroll
        for (int ks = 0; ks < 16; ks++) {
            const int k0 = ks * 8;
            uint32_t a[4][4], bf[4][2];
#pragma unroll
            for (int mi = 0; mi < 4; mi++) {
                int r0 = warp_m * 64 + mi * 16 + qid;
                a[mi][0] = __float_as_uint(As[r0 * TPAD + k0 + tig]);
                a[mi][1] = __float_as_uint(As[(r0 + 8) * TPAD + k0 + tig]);
                a[mi][2] = __float_as_uint(As[r0 * TPAD + k0 + tig + 4]);
                a[mi][3] = __float_as_uint(As[(r0 + 8) * TPAD + k0 + tig + 4]);
            }
#pragma unroll
            for (int ni = 0; ni < 4; ni++) {
                int bn = warp_n * 32 + ni * 8 + qid;
                bf[ni][0] = __float_as_uint(Bs[bn * TPAD + k0 + tig]);
                bf[ni][1] = __float_as_uint(Bs[bn * TPAD + k0 + tig + 4]);
            }
#pragma unroll
            for (int mi = 0; mi < 4; mi++)
#pragma unroll
                for (int ni = 0; ni < 4; ni++)
                    asm volatile(
                        "mma.sync.aligned.m16n8k8.row.col.f32.tf32.tf32.f32 "
                        "{%0,%1,%2,%3},{%4,%5,%6,%7},{%8,%9},{%0,%1,%2,%3};"
                        : "+f"(c[mi][ni][0]), "+f"(c[mi][ni][1]),
                          "+f"(c[mi][ni][2]), "+f"(c[mi][ni][3])
                        : "r"(a[mi][0]), "r"(a[mi][1]), "r"(a[mi][2]), "r"(a[mi][3]),
                          "r"(bf[ni][0]), "r"(bf[ni][1]));
        }

        // ---- epilogue: direct STG (32B-sector coalesced) + row partials ----
        const int n0 = nt * 128;
        const int nvalid = min(128, V_ - n0);

#pragma unroll
        for (int mi = 0; mi < 4; mi++) {
            const int r0 = m0 + warp_m * 64 + mi * 16 + qid;
            float mxa = -INFINITY, mxb = -INFINITY;
#pragma unroll
            for (int ni = 0; ni < 4; ni++) {
                const int c0 = warp_n * 32 + ni * 8 + tig * 2;
                const bool ok0 = (c0 < nvalid), ok1 = (c0 + 1 < nvalid);
                if (ok0) {
                    out[(size_t)r0 * V_ + n0 + c0]       = c[mi][ni][0];
                    out[(size_t)(r0 + 8) * V_ + n0 + c0] = c[mi][ni][2];
                    mxa = fmaxf(mxa, c[mi][ni][0]);
                    mxb = fmaxf(mxb, c[mi][ni][2]);
                }
                if (ok1) {
                    out[(size_t)r0 * V_ + n0 + c0 + 1]       = c[mi][ni][1];
                    out[(size_t)(r0 + 8) * V_ + n0 + c0 + 1] = c[mi][ni][3];
                    mxa = fmaxf(mxa, c[mi][ni][1]);
                    mxb = fmaxf(mxb, c[mi][ni][3]);
                }
            }
            mxa = fmaxf(mxa, __shfl_xor_sync(0xffffffffu, mxa, 1));
            mxa = fmaxf(mxa, __shfl_xor_sync(0xffffffffu, mxa, 2));
            mxb = fmaxf(mxb, __shfl_xor_sync(0xffffffffu, mxb, 1));
            mxb = fmaxf(mxb, __shfl_xor_sync(0xffffffffu, mxb, 2));
            float sa = 0.f, sb = 0.f;
#pragma unroll
            for (int ni = 0; ni < 4; ni++) {
                const int c0 = warp_n * 32 + ni * 8 + tig * 2;
                if (c0 < nvalid)     { sa += __expf(c[mi][ni][0] - mxa);
                                       sb += __expf(c[mi][ni][2] - mxb); }
                if (c0 + 1 < nvalid) { sa += __expf(c[mi][ni][1] - mxa);
                                       sb += __expf(c[mi][ni][3] - mxb); }
            }
            sa += __shfl_xor_sync(0xffffffffu, sa, 1);
            sa += __shfl_xor_sync(0xffffffffu, sa, 2);
            sb += __shfl_xor_sync(0xffffffffu, sb, 1);
            sb += __shfl_xor_sync(0xffffffffu, sb, 2);
            if (tig == 0) {
                prt[(warp_m * 64 + mi * 16 + qid) * 4 + warp_n]     = make_float2(mxa, sa);
                prt[(warp_m * 64 + mi * 16 + qid + 8) * 4 + warp_n] = make_float2(mxb, sb);
            }
        }
        __syncthreads();
        if (tid < 128) {
            float m = -INFINITY, l = 0.f;
#pragma unroll
            for (int w = 0; w < 4; w++) {
                float2 p = prt[tid * 4 + w];
                float nm = fmaxf(m, p.x);
                l = l * __expf(m - nm) + p.y * __expf(p.x - nm);
                m = nm;
            }
            g_part[(size_t)(m0 + tid) * NT_ + nt] = make_float2(m, l);
        }
        __syncthreads();
    }
}

// ---------------- K4: combine partials -> lse[b] ----------------------------
__global__ void lse_kernel() {
    const int b = blockIdx.x, t = threadIdx.x;   // 128 threads
    __shared__ float sm_[128], sl[128];
    float m = -INFINITY, l = 0.f;
    for (int i = t; i < NT_; i += 128) {
        float2 p = g_part[(size_t)b * NT_ + i];
        float nm = fmaxf(m, p.x);
        l = l * expf(m - nm) + p.y * expf(p.x - nm);
        m = nm;
    }
    sm_[t] = m; sl[t] = l;
    __syncthreads();
    for (int s = 64; s > 0; s >>= 1) {
        if (t < s) {
            float m2 = sm_[t + s], l2 = sl[t + s];
            float nm = fmaxf(sm_[t], m2);
            sl[t] = sl[t] * expf(sm_[t] - nm) + l2 * expf(m2 - nm);
            sm_[t] = nm;
        }
        __syncthreads();
    }
    if (t == 0) g_lse[b] = sm_[0] + logf(sl[0]);
}

// ---------------- K5: out -= lse[b], vectorized ------------------------------
__global__ void sub_kernel(float4* __restrict__ out4) {
    const long n4 = (long)B_ * V_ / 4;
    for (long i = blockIdx.x * (long)blockDim.x + threadIdx.x; i < n4;
         i += (long)gridDim.x * blockDim.x) {
        long p = i * 4;
        int  b = (int)(p / V_);
        long rem = p - (long)b * V_;
        float4 v = out4[i];
        if (rem + 3 < V_) {
            float ls = g_lse[b];
            v.x -= ls; v.y -= ls; v.z -= ls; v.w -= ls;
        } else {
            v.x -= g_lse[b];
            v.y -= g_lse[(p + 1) / V_];
            v.z -= g_lse[(p + 2) / V_];
            v.w -= g_lse[(p + 3) / V_];
        }
        out4[i] = v;
    }
}

extern "C" void kernel_launch(void* const* d_in, const int* in_sizes, int n_in,
                              void* d_out, int out_size) {
    const float* xs     = (const float*)d_in[0];
    const float* metric = (const float*)d_in[1];
    const float* EMB    = (const float*)d_in[2];
    const float* NEG    = (const float*)d_in[3];
    float* out = (float*)d_out;

    find_idx_kernel<<<2048, 256>>>((const float4*)xs);
    embed_metric_kernel<<<B_, 128>>>(EMB, metric);

    cudaFuncSetAttribute(gemm_lse_tc,
                         cudaFuncAttributeMaxDynamicSharedMemorySize, SMEM_BYTES);
    gemm_lse_tc<<<dim3(19, 8), 256, SMEM_BYTES>>>(NEG, out);

    lse_kernel<<<B_, 128>>>();
    sub_kernel<<<2048, 256>>>((float4*)out);
}

// round 4
// speedup vs baseline: 1.3870x; 1.0991x over previous
#include <cuda_runtime.h>
#include <cuda_fp16.h>
#include <cstdint>
#include <math.h>

#define B_  1024
#define V_  50257
#define E_  128
#define NT_ 393          // ceil(V_/128)
#define VP_ (NT_ * 128)  // 50304 padded rows

// ---- scratch (no allocations allowed) ----
__device__ int     g_idx[B_];
__device__ __half  g_yh[B_ * E_];
__device__ __half  g_negh[(size_t)VP_ * E_];   // padded half copy of NEGEMBEDM
__device__ float2  g_part[B_ * NT_];
__device__ float   g_lse[B_];

__device__ __forceinline__ uint32_t smem_u32(const void* p) {
    uint32_t a;
    asm("{ .reg .u64 t; cvta.to.shared.u64 t, %1; cvt.u32.u64 %0, t; }"
        : "=r"(a) : "l"(p));
    return a;
}

// ---------------- K1: recover one-hot indices (bandwidth-bound scan) --------
__global__ void find_idx_kernel(const float4* __restrict__ xs4) {
    const long n4 = (long)B_ * V_ / 4;
    for (long i = blockIdx.x * (long)blockDim.x + threadIdx.x; i < n4;
         i += (long)gridDim.x * blockDim.x) {
        float4 v = xs4[i];
        if (v.x != 0.f || v.y != 0.f || v.z != 0.f || v.w != 0.f) {
            float vals[4] = {v.x, v.y, v.z, v.w};
            long base = i * 4;
#pragma unroll
            for (int j = 0; j < 4; j++) {
                if (vals[j] != 0.f) {
                    long p = base + j;
                    int  b = (int)(p / V_);
                    g_idx[b] = (int)(p - (long)b * V_);
                }
            }
        }
    }
}

// ---------------- K1b: convert NEGEMBEDM fp32 -> padded half ----------------
__global__ void conv_neg_kernel(const float4* __restrict__ neg4) {
    // each iter handles 8 halves (16B out, 32B in)
    const long n8 = (long)VP_ * E_ / 8;
    for (long i = blockIdx.x * (long)blockDim.x + threadIdx.x; i < n8;
         i += (long)gridDim.x * blockDim.x) {
        long row = (i * 8) / E_;
        uint2 o;
        if (row < V_) {
            float4 v0 = neg4[i * 2];
            float4 v1 = neg4[i * 2 + 1];
            __half2 h0 = __float22half2_rn(make_float2(v0.x, v0.y));
            __half2 h1 = __float22half2_rn(make_float2(v0.z, v0.w));
            __half2 h2 = __float22half2_rn(make_float2(v1.x, v1.y));
            __half2 h3 = __float22half2_rn(make_float2(v1.z, v1.w));
            o = make_uint2(*(uint32_t*)&h0 | (*(uint32_t*)&h1 << 0), 0);
            uint32_t w0 = (*(uint32_t*)&h0) | ((*(uint32_t*)&h1) << 16);
            uint32_t w1 = (*(uint32_t*)&h2) | ((*(uint32_t*)&h3) << 16);
            // __half2 already packs 2 halves in 32 bits; rebuild properly:
            w0 = *reinterpret_cast<uint32_t*>(&h0);
            w1 = *reinterpret_cast<uint32_t*>(&h1);
            uint32_t w2 = *reinterpret_cast<uint32_t*>(&h2);
            uint32_t w3 = *reinterpret_cast<uint32_t*>(&h3);
            uint4 out = make_uint4(w0, w1, w2, w3);
            *reinterpret_cast<uint4*>(g_negh + i * 8) = out;
            continue;
        } else {
            *reinterpret_cast<uint4*>(g_negh + i * 8) = make_uint4(0, 0, 0, 0);
        }
        (void)o;
    }
}

// ---------------- K2: y[b] = EMBEDM[idx[b]] @ metric -> half ----------------
__global__ void embed_metric_kernel(const float* __restrict__ EMB,
                                    const float* __restrict__ metric) {
    __shared__ float xe[E_];
    const int b = blockIdx.x, t = threadIdx.x;   // 128 threads
    const int idx = g_idx[b];
    xe[t] = EMB[(size_t)idx * E_ + t];
    __syncthreads();
    float acc = 0.f;
#pragma unroll 8
    for (int k = 0; k < E_; k++) acc += xe[k] * metric[k * E_ + t];
    g_yh[b * E_ + t] = __float2half_rn(acc);
}

// ---------------- K3: persistent fp16 mma.sync GEMM + partials --------------
// smem: A half[128][128] swizzled @0 (32KB) | B0 @32768 | B1 @65536 | prt @98304
#define SM_A   0
#define SM_B0  32768
#define SM_B1  65536
#define SM_P   98304
#define SMEM_BYTES (98304 + 4096)

// swizzled byte offset for (row, 16B-chunk c8) in a [128][256B] tile
__device__ __forceinline__ uint32_t swz(int row, int c8) {
    return (uint32_t)(row * 256 + ((c8 ^ (row & 7)) << 4));
}

__global__ void __launch_bounds__(256, 1)
gemm_lse_tc(float* __restrict__ out) {
    extern __shared__ char smc[];
    float2* prt = reinterpret_cast<float2*>(smc + SM_P);
    const uint32_t sbase = smem_u32(smc);

    const int tid = threadIdx.x;
    const int wid = tid >> 5, lane = tid & 31;
    const int warp_m = wid & 1, warp_n = wid >> 1;
    const int qid = lane >> 2, tig = lane & 3;
    const int m0 = blockIdx.y * 128;

    // ---- load A tile once (g_yh m-block) into swizzled smem ----
    {
        const int r = tid >> 1;                   // 2 chunks per thread? 2048/256=8
#pragma unroll
        for (int f = tid; f < 2048; f += 256) {
            int row = f >> 4, c8 = f & 15;
            uint4 v = *reinterpret_cast<const uint4*>(g_yh + (m0 + row) * E_ + c8 * 8);
            *reinterpret_cast<uint4*>(smc + SM_A + swz(row, c8)) = v;
        }
        (void)r;
    }

    // issue cp.async for B tile nt into buffer buf (data pre-padded)
    auto issueB = [&](int nt, int buf) {
        const int n0 = nt * 128;
        const uint32_t d0 = sbase + (buf ? SM_B1 : SM_B0);
#pragma unroll
        for (int f = tid; f < 2048; f += 256) {
            int row = f >> 4, c8 = f & 15;
            uint32_t dst = d0 + swz(row, c8);
            const char* src = reinterpret_cast<const char*>(g_negh)
                            + (size_t)(n0 + row) * 256 + c8 * 16;
            asm volatile("cp.async.cg.shared.global [%0], [%1], 16;"
                         :: "r"(dst), "l"(src) : "memory");
        }
        asm volatile("cp.async.commit_group;" ::: "memory");
    };

    issueB(blockIdx.x, 0);
    int buf = 0;
    for (int nt = blockIdx.x; nt < NT_; nt += gridDim.x, buf ^= 1) {
        const int ntn = nt + gridDim.x;
        if (ntn < NT_) issueB(ntn, buf ^ 1);
        else asm volatile("cp.async.commit_group;" ::: "memory");
        asm volatile("cp.async.wait_group 1;" ::: "memory");
        __syncthreads();

        const uint32_t aB = sbase + SM_A;
        const uint32_t bB = sbase + (buf ? SM_B1 : SM_B0);

        float c[4][4][4];
#pragma unroll
        for (int mi = 0; mi < 4; mi++)
#pragma unroll
            for (int ni = 0; ni < 4; ni++)
#pragma unroll
                for (int j = 0; j < 4; j++) c[mi][ni][j] = 0.f;

#pragma unroll
        for (int ks = 0; ks < 8; ks++) {
            const int c8a = ks * 2 + (lane >> 4);           // A: lanes 16-31 -> k0+8
            const int c8b = ks * 2 + ((lane >> 3) & 1);     // B: lanes 8-15  -> k0+8
            uint32_t a[4][4], b[4][2];
#pragma unroll
            for (int mi = 0; mi < 4; mi++) {
                int row = warp_m * 64 + mi * 16 + (lane & 15);
                uint32_t addr = aB + swz(row, c8a);
                asm volatile("ldmatrix.sync.aligned.m8n8.x4.shared.b16 "
                             "{%0,%1,%2,%3}, [%4];"
                             : "=r"(a[mi][0]), "=r"(a[mi][1]),
                               "=r"(a[mi][2]), "=r"(a[mi][3]) : "r"(addr));
            }
#pragma unroll
            for (int ni = 0; ni < 4; ni++) {
                int nrow = warp_n * 32 + ni * 8 + (lane & 7);
                uint32_t addr = bB + swz(nrow, c8b);
                asm volatile("ldmatrix.sync.aligned.m8n8.x2.shared.b16 "
                             "{%0,%1}, [%2];"
                             : "=r"(b[ni][0]), "=r"(b[ni][1]) : "r"(addr));
            }
#pragma unroll
            for (int mi = 0; mi < 4; mi++)
#pragma unroll
                for (int ni = 0; ni < 4; ni++)
                    asm volatile(
                        "mma.sync.aligned.m16n8k16.row.col.f32.f16.f16.f32 "
                        "{%0,%1,%2,%3},{%4,%5,%6,%7},{%8,%9},{%0,%1,%2,%3};"
                        : "+f"(c[mi][ni][0]), "+f"(c[mi][ni][1]),
                          "+f"(c[mi][ni][2]), "+f"(c[mi][ni][3])
                        : "r"(a[mi][0]), "r"(a[mi][1]), "r"(a[mi][2]), "r"(a[mi][3]),
                          "r"(b[ni][0]), "r"(b[ni][1]));
        }

        // ---- epilogue: direct STG + row partials ----
        const int n0 = nt * 128;
        const int nvalid = min(128, V_ - n0);

#pragma unroll
        for (int mi = 0; mi < 4; mi++) {
            const int r0 = m0 + warp_m * 64 + mi * 16 + qid;
            float mxa = -INFINITY, mxb = -INFINITY;
#pragma unroll
            for (int ni = 0; ni < 4; ni++) {
                const int c0 = warp_n * 32 + ni * 8 + tig * 2;
                const bool ok0 = (c0 < nvalid), ok1 = (c0 + 1 < nvalid);
                if (ok0) {
                    out[(size_t)r0 * V_ + n0 + c0]       = c[mi][ni][0];
                    out[(size_t)(r0 + 8) * V_ + n0 + c0] = c[mi][ni][2];
                    mxa = fmaxf(mxa, c[mi][ni][0]);
                    mxb = fmaxf(mxb, c[mi][ni][2]);
                }
                if (ok1) {
                    out[(size_t)r0 * V_ + n0 + c0 + 1]       = c[mi][ni][1];
                    out[(size_t)(r0 + 8) * V_ + n0 + c0 + 1] = c[mi][ni][3];
                    mxa = fmaxf(mxa, c[mi][ni][1]);
                    mxb = fmaxf(mxb, c[mi][ni][3]);
                }
            }
            mxa = fmaxf(mxa, __shfl_xor_sync(0xffffffffu, mxa, 1));
            mxa = fmaxf(mxa, __shfl_xor_sync(0xffffffffu, mxa, 2));
            mxb = fmaxf(mxb, __shfl_xor_sync(0xffffffffu, mxb, 1));
            mxb = fmaxf(mxb, __shfl_xor_sync(0xffffffffu, mxb, 2));
            float sa = 0.f, sb = 0.f;
#pragma unroll
            for (int ni = 0; ni < 4; ni++) {
                const int c0 = warp_n * 32 + ni * 8 + tig * 2;
                if (c0 < nvalid)     { sa += __expf(c[mi][ni][0] - mxa);
                                       sb += __expf(c[mi][ni][2] - mxb); }
                if (c0 + 1 < nvalid) { sa += __expf(c[mi][ni][1] - mxa);
                                       sb += __expf(c[mi][ni][3] - mxb); }
            }
            sa += __shfl_xor_sync(0xffffffffu, sa, 1);
            sa += __shfl_xor_sync(0xffffffffu, sa, 2);
            sb += __shfl_xor_sync(0xffffffffu, sb, 1);
            sb += __shfl_xor_sync(0xffffffffu, sb, 2);
            if (tig == 0) {
                prt[(warp_m * 64 + mi * 16 + qid) * 4 + warp_n]     = make_float2(mxa, sa);
                prt[(warp_m * 64 + mi * 16 + qid + 8) * 4 + warp_n] = make_float2(mxb, sb);
            }
        }
        __syncthreads();
        if (tid < 128) {
            float m = -INFINITY, l = 0.f;
#pragma unroll
            for (int w = 0; w < 4; w++) {
                float2 p = prt[tid * 4 + w];
                float nm = fmaxf(m, p.x);
                l = l * __expf(m - nm) + p.y * __expf(p.x - nm);
                m = nm;
            }
            g_part[(size_t)(m0 + tid) * NT_ + nt] = make_float2(m, l);
        }
        __syncthreads();
    }
}

// ---------------- K4: combine partials -> lse[b] ----------------------------
__global__ void lse_kernel() {
    const int b = blockIdx.x, t = threadIdx.x;   // 128 threads
    __shared__ float sm_[128], sl[128];
    float m = -INFINITY, l = 0.f;
    for (int i = t; i < NT_; i += 128) {
        float2 p = g_part[(size_t)b * NT_ + i];
        float nm = fmaxf(m, p.x);
        l = l * expf(m - nm) + p.y * expf(p.x - nm);
        m = nm;
    }
    sm_[t] = m; sl[t] = l;
    __syncthreads();
    for (int s = 64; s > 0; s >>= 1) {
        if (t < s) {
            float m2 = sm_[t + s], l2 = sl[t + s];
            float nm = fmaxf(sm_[t], m2);
            sl[t] = sl[t] * expf(sm_[t] - nm) + l2 * expf(m2 - nm);
            sm_[t] = nm;
        }
        __syncthreads();
    }
    if (t == 0) g_lse[b] = sm_[0] + logf(sl[0]);
}

// ---------------- K5: out -= lse[b], vectorized ------------------------------
__global__ void sub_kernel(float4* __restrict__ out4) {
    const long n4 = (long)B_ * V_ / 4;
    for (long i = blockIdx.x * (long)blockDim.x + threadIdx.x; i < n4;
         i += (long)gridDim.x * blockDim.x) {
        long p = i * 4;
        int  b = (int)(p / V_);
        long rem = p - (long)b * V_;
        float4 v = out4[i];
        if (rem + 3 < V_) {
            float ls = g_lse[b];
            v.x -= ls; v.y -= ls; v.z -= ls; v.w -= ls;
        } else {
            v.x -= g_lse[b];
            v.y -= g_lse[(p + 1) / V_];
            v.z -= g_lse[(p + 2) / V_];
            v.w -= g_lse[(p + 3) / V_];
        }
        out4[i] = v;
    }
}

extern "C" void kernel_launch(void* const* d_in, const int* in_sizes, int n_in,
                              void* d_out, int out_size) {
    const float* xs     = (const float*)d_in[0];
    const float* metric = (const float*)d_in[1];
    const float* EMB    = (const float*)d_in[2];
    const float* NEG    = (const float*)d_in[3];
    float* out = (float*)d_out;

    conv_neg_kernel<<<1024, 256>>>((const float4*)NEG);
    find_idx_kernel<<<2048, 256>>>((const float4*)xs);
    embed_metric_kernel<<<B_, 128>>>(EMB, metric);

    cudaFuncSetAttribute(gemm_lse_tc,
                         cudaFuncAttributeMaxDynamicSharedMemorySize, SMEM_BYTES);
    gemm_lse_tc<<<dim3(19, 8), 256, SMEM_BYTES>>>(out);

    lse_kernel<<<B_, 128>>>();
    sub_kernel<<<2048, 256>>>((float4*)out);
}